// round 5
// baseline (speedup 1.0000x reference)
#include <cuda_runtime.h>
#include <cuda_fp16.h>
#include <cstdint>

// ---------------- problem constants ----------------
#define NB     4096
#define NPOL   3849
#define NDROP  7
#define SCALE  0.0625f          // 1/sqrt(256)

// ---------------- smem layout (bytes), per CTA (2 batches) ----------------
// R1: X fp16 [192 rows][512B]  -> later: board0 f32[96][96] @+0, board1 @+36864, S_j fp16 [192][128B] @+73728
// R2: PE fp16 [192 rows][512B]
// R3: weight chunks, 2 x 16KB ([64 n][128 k] fp16, 256B rows)
#define R1       0u
#define R2       98304u
#define R3       196608u
#define OFF_S    73728u          // within R1
#define SMEM_TOT 229376u

// ---------------- device scratch ----------------
__device__ __align__(128) __half g_WE  [256*256];   // We^T  [n][k]
__device__ __align__(128) __half g_W2  [256*256];   // SCALE*(Wq Wk^T)^T  [n][k]
__device__ __align__(128) __half g_SEXT[10*256];    // S_ext rows 81..90
__device__ float g_CONST[16];                        // [0]=cQK [1..7]=cdrop [8]=ckwp
__device__ int g_MAP[NPOL];

// ---------------- helpers ----------------
__device__ __forceinline__ uint32_t swz128(uint32_t o) { return o ^ ((o >> 3) & 0x70); }
__device__ __forceinline__ uint32_t swz256(uint32_t o) { return o ^ ((o >> 4) & 0x70); }
__device__ __forceinline__ uint32_t swz512(uint32_t o) { return o ^ ((o >> 5) & 0x70); }

__device__ __forceinline__ uint32_t pack2(float a, float b) {
    __half2 h = __floats2half2_rn(a, b);
    return *reinterpret_cast<uint32_t*>(&h);
}

__device__ __forceinline__ void ldsm4(uint32_t& r0, uint32_t& r1, uint32_t& r2, uint32_t& r3, uint32_t addr) {
    asm volatile("ldmatrix.sync.aligned.m8n8.x4.shared.b16 {%0,%1,%2,%3}, [%4];\n"
                 : "=r"(r0), "=r"(r1), "=r"(r2), "=r"(r3) : "r"(addr));
}

__device__ __forceinline__ void mma16816(float* c, uint32_t a0, uint32_t a1, uint32_t a2, uint32_t a3,
                                         uint32_t b0, uint32_t b1) {
    asm volatile("mma.sync.aligned.m16n8k16.row.col.f32.f16.f16.f32 "
                 "{%0,%1,%2,%3},{%4,%5,%6,%7},{%8,%9},{%0,%1,%2,%3};\n"
                 : "+f"(c[0]), "+f"(c[1]), "+f"(c[2]), "+f"(c[3])
                 : "r"(a0), "r"(a1), "r"(a2), "r"(a3), "r"(b0), "r"(b1));
}

__device__ __forceinline__ float mishf(float v) {
    float e  = __expf(v);
    float sp = (v > 15.f) ? v : __logf(1.f + e);
    float z  = __expf(-2.f * sp);
    float t  = __fdividef(1.f - z, 1.f + z);
    return v * t;
}

__device__ __forceinline__ void cp_async16(uint32_t dst, const void* src) {
    asm volatile("cp.async.cg.shared.global [%0], [%1], 16;\n" :: "r"(dst), "l"(src));
}
__device__ __forceinline__ void cp_commit() { asm volatile("cp.async.commit_group;\n" ::: "memory"); }
template<int N> __device__ __forceinline__ void cp_wait() {
    asm volatile("cp.async.wait_group %0;\n" :: "n"(N) : "memory");
}

// ---------------- unified prep kernel ----------------
__global__ void prep_all(const float* __restrict__ We, const float* __restrict__ Wq,
                         const float* __restrict__ Wk, const float* __restrict__ Wp,
                         const float* __restrict__ bq, const float* __restrict__ bk,
                         const float* __restrict__ bp, const float* __restrict__ dqm,
                         const void* __restrict__ rawp, const void* __restrict__ polp) {
    __shared__ float wkrow[256];
    int bid = blockIdx.x, tid = threadIdx.x;
    int lane = tid & 31, w = tid >> 5;

    if (bid < 256) {
        // g_WE row n + g_W2 row n
        int n = bid, k = tid;
        g_WE[n*256 + k] = __float2half(We[k*256 + n]);
        wkrow[k] = Wk[n*256 + k];
        __syncthreads();
        const float4* wq = (const float4*)(Wq + (size_t)k * 256);
        float s = 0.f;
        #pragma unroll 8
        for (int o = 0; o < 64; ++o) {
            float4 q = wq[o];
            s += q.x * wkrow[4*o] + q.y * wkrow[4*o+1] + q.z * wkrow[4*o+2] + q.w * wkrow[4*o+3];
        }
        g_W2[n*256 + k] = __float2half(s * SCALE);
    } else if (bid < 512) {
        // S_ext column j: warps 0-7 -> t=w; warps 0,1 second pass -> t=8,9
        int j = bid - 256;
        #pragma unroll
        for (int pass = 0; pass < 2; ++pass) {
            int t = (pass == 0) ? w : ((w < 2) ? 8 + w : -1);
            if (t < 0) continue;
            float s = 0.f;
            for (int o = lane; o < 256; o += 32) {
                float term;
                if (t < 7)       term = dqm[t*256 + o] * Wk[j*256 + o];
                else if (t == 7) term = Wk[j*256 + o] * Wp[o];
                else if (t == 8) term = Wk[j*256 + o] * bq[o];
                else             term = Wq[j*256 + o] * bk[o];
                s += term;
            }
            #pragma unroll
            for (int off = 16; off; off >>= 1) s += __shfl_xor_sync(0xffffffffu, s, off);
            if (lane == 0) g_SEXT[t*256 + j] = __float2half((t == 7) ? s : s * SCALE);
        }
    } else if (bid == 512) {
        // constants: warp 0 -> cQK + ckwp; warps 1-7 -> cdrop
        #pragma unroll
        for (int pass = 0; pass < 2; ++pass) {
            float s = 0.f;
            int which = -1;
            if (pass == 0) {
                if (w == 0) { for (int o = lane; o < 256; o += 32) s += bq[o] * bk[o]; which = 0; }
                else        { for (int o = lane; o < 256; o += 32) s += dqm[(w-1)*256 + o] * bk[o]; which = w; }
            } else if (w == 0) {
                for (int o = lane; o < 256; o += 32) s += bk[o] * Wp[o];
                which = 8;
            }
            if (which < 0) continue;
            #pragma unroll
            for (int off = 16; off; off >>= 1) s += __shfl_xor_sync(0xffffffffu, s, off);
            if (lane == 0) g_CONST[which] = (which == 8) ? (s + bp[0]) : (s * SCALE);
        }
    } else {
        int j = (bid - 513) * 256 + tid;
        if (j < NPOL) {
            const int* r32 = (const int*)rawp;
            bool is64 = (r32[1] == 0 && r32[3] == 0 && r32[5] == 0 && r32[7] == 0);
            long long rv, pv;
            if (is64) { rv = ((const long long*)rawp)[j]; pv = ((const long long*)polp)[j]; }
            else      { rv = r32[j];                      pv = ((const int*)polp)[j]; }
            g_MAP[(int)pv] = (int)rv;
        }
    }
}

// ---------------- fused-kernel building blocks ----------------
// prefetch one [64n][128k] fp16 chunk (16KB, 256B rows swz256) of W row-block j, k-half kc
__device__ __forceinline__ void pf_chunk(uint32_t sbase, const __half* __restrict__ W,
                                         int j, int kc, int buf, int tid) {
    #pragma unroll
    for (int t = 0; t < 3; ++t) {
        int i = tid + t * 384;
        if (i < 1024) {
            int r = i >> 4, c = i & 15;
            cp_async16(sbase + R3 + (uint32_t)buf * 16384u + swz256((uint32_t)(r * 256 + c * 16)),
                       W + (size_t)(j * 64 + r) * 256 + kc * 128 + c * 8);
        }
    }
    cp_commit();
}

// one 128-k sub-chunk of a 192x64 tile GEMM; A @ aOff (512B rows swz512), B chunk @ bOff
__device__ __forceinline__ void mma_sub(float acc[2][4][4], uint32_t sbase, uint32_t aOff,
                                        int kc, uint32_t bOff, int lane, int wm, int wn) {
    #pragma unroll
    for (int ks = 0; ks < 8; ++ks) {
        uint32_t a[2][4];
        #pragma unroll
        for (int i = 0; i < 2; ++i) {
            uint32_t off = swz512((uint32_t)((wm*32 + i*16 + (lane & 15)) * 512
                                             + kc*256 + ks*32 + ((lane >> 4) << 4)));
            ldsm4(a[i][0], a[i][1], a[i][2], a[i][3], sbase + aOff + off);
        }
        #pragma unroll
        for (int j2 = 0; j2 < 2; ++j2) {
            uint32_t b0, b1, b2, b3;
            uint32_t n = (uint32_t)(wn*32 + j2*16 + (lane & 7) + ((lane >> 4) << 3));
            uint32_t off = swz256(n * 256 + ks*32 + (((lane >> 3) & 1) << 4));
            ldsm4(b0, b1, b2, b3, sbase + bOff + off);
            #pragma unroll
            for (int i = 0; i < 2; ++i) {
                mma16816(acc[i][j2*2],   a[i][0], a[i][1], a[i][2], a[i][3], b0, b1);
                mma16816(acc[i][j2*2+1], a[i][0], a[i][1], a[i][2], a[i][3], b2, b3);
            }
        }
    }
}

// GEMM3 partial for tile j: board_b += S_j[96b..][64] * PE_b[:, 64j..]^T
__device__ __forceinline__ void gemm3_part(float acc3[12][4], uint32_t sbase, int j,
                                           int lane, int bb, int wm3) {
    #pragma unroll
    for (int ks = 0; ks < 4; ++ks) {
        uint32_t a0, a1, a2, a3;
        uint32_t aoff = swz128((uint32_t)((bb*96 + wm3*16 + (lane & 15)) * 128
                                          + ks*32 + ((lane >> 4) << 4)));
        ldsm4(a0, a1, a2, a3, sbase + R1 + OFF_S + aoff);
        #pragma unroll
        for (int jb = 0; jb < 6; ++jb) {
            uint32_t b0, b1, b2, b3;
            uint32_t n = (uint32_t)(jb*16 + (lane & 7) + ((lane >> 4) << 3));
            uint32_t boff = swz512((uint32_t)((bb*96 + n) * 512 + j*128 + ks*32
                                              + (((lane >> 3) & 1) << 4)));
            ldsm4(b0, b1, b2, b3, sbase + R2 + boff);
            mma16816(acc3[jb*2],   a0, a1, a2, a3, b0, b1);
            mma16816(acc3[jb*2+1], a0, a1, a2, a3, b2, b3);
        }
    }
}

// ---------------- fused kernel: one CTA per 2 batches ----------------
__global__ void __launch_bounds__(384, 1) k_fused(const float* __restrict__ X,
                                                  const float* __restrict__ be,
                                                  float* __restrict__ out) {
    extern __shared__ char sm[];
    uint32_t sbase = (uint32_t)__cvta_generic_to_shared(sm);
    int tid = threadIdx.x, lane = tid & 31, w = tid >> 5;
    int wm = w >> 1, wn = w & 1;              // GEMM1/2: 6m x 2n, warp tile 32x32
    int rl = lane >> 2, cl = (lane & 3) * 2;

    // ---- weights chunk0 in flight; X (2 batches, f32->fp16, pad rows) into R1 ----
    pf_chunk(sbase, g_WE, 0, 0, 0, tid);
    for (int idx = tid; idx < 6144; idx += 384) {
        int r = idx >> 5, c = idx & 31;
        int loc = (r < 96) ? r : r - 96;
        uint4 u = make_uint4(0u, 0u, 0u, 0u);
        if (loc < 81) {
            size_t grow = (size_t)(blockIdx.x * 2 + (r >= 96)) * 81 + loc;
            const float4* p = (const float4*)(X + grow * 256 + c * 8);
            float4 f0 = p[0], f1 = p[1];
            u.x = pack2(f0.x, f0.y); u.y = pack2(f0.z, f0.w);
            u.z = pack2(f1.x, f1.y); u.w = pack2(f1.z, f1.w);
        }
        *(uint4*)(sm + R1 + swz512((uint32_t)(r * 512 + c * 16))) = u;
    }

    // ---- GEMM1: PE = mish(X @ We^T + be), X @R1 -> PE @R2, n-tiles of 64 ----
    for (int j = 0; j < 4; ++j) {
        float acc[2][4][4] = {};
        #pragma unroll
        for (int kc = 0; kc < 2; ++kc) {
            int u = j * 2 + kc;
            if (u < 7) { pf_chunk(sbase, g_WE, (u+1) >> 1, (u+1) & 1, (u+1) & 1, tid); cp_wait<1>(); }
            else       { cp_wait<0>(); }
            __syncthreads();
            mma_sub(acc, sbase, R1, kc, R3 + (uint32_t)(u & 1) * 16384u, lane, wm, wn);
            __syncthreads();
        }
        if (j == 3) pf_chunk(sbase, g_W2, 0, 0, 0, tid);   // overlap with epilogue
        #pragma unroll
        for (int i = 0; i < 2; ++i) {
            int r = wm*32 + i*16 + rl;
            #pragma unroll
            for (int jj = 0; jj < 4; ++jj) {
                int gcol = j*64 + wn*32 + jj*8 + cl;
                float b0 = __ldg(be + gcol), b1 = __ldg(be + gcol + 1);
                *(uint32_t*)(sm + R2 + swz512((uint32_t)(r * 512 + gcol * 2))) =
                    pack2(mishf(acc[i][jj][0] + b0), mishf(acc[i][jj][1] + b1));
                *(uint32_t*)(sm + R2 + swz512((uint32_t)((r + 8) * 512 + gcol * 2))) =
                    pack2(mishf(acc[i][jj][2] + b0), mishf(acc[i][jj][3] + b1));
            }
        }
    }

    // ---- GEMM2 (tiled) fused with GEMM3: boards accumulate in registers ----
    float acc3[12][4] = {};
    int bb = w / 6, wm3 = w % 6;               // GEMM3: 6 warps per batch, tile 16x96
    for (int j = 0; j < 4; ++j) {
        float acc[2][4][4] = {};
        #pragma unroll
        for (int kc = 0; kc < 2; ++kc) {
            int u = j * 2 + kc;
            if (u < 7) { pf_chunk(sbase, g_W2, (u+1) >> 1, (u+1) & 1, (u+1) & 1, tid); cp_wait<1>(); }
            else       { cp_wait<0>(); }
            __syncthreads();
            mma_sub(acc, sbase, R2, kc, R3 + (uint32_t)(u & 1) * 16384u, lane, wm, wn);
            __syncthreads();
        }
        // S_j epilogue -> fp16 staging (skip per-batch rows >= 81; SEXT/zeros fill them)
        #pragma unroll
        for (int i = 0; i < 2; ++i) {
            int r = wm*32 + i*16 + rl;
            #pragma unroll
            for (int jj = 0; jj < 4; ++jj) {
                int lcol = wn*32 + jj*8 + cl;
                if ((r % 96) < 81)
                    *(uint32_t*)(sm + R1 + OFF_S + swz128((uint32_t)(r * 128 + lcol * 2))) =
                        pack2(acc[i][jj][0], acc[i][jj][1]);
                if (((r + 8) % 96) < 81)
                    *(uint32_t*)(sm + R1 + OFF_S + swz128((uint32_t)((r + 8) * 128 + lcol * 2))) =
                        pack2(acc[i][jj][2], acc[i][jj][3]);
            }
        }
        if (tid < 240) {                        // S_ext rows 81-90 (+zeros 91-95), both batches
            int bb2 = tid / 120, rem = tid % 120, t = rem >> 3, c = rem & 7;
            uint4 v = make_uint4(0u, 0u, 0u, 0u);
            if (t < 10) v = *(const uint4*)&g_SEXT[t * 256 + j * 64 + c * 8];
            *(uint4*)(sm + R1 + OFF_S + swz128((uint32_t)((bb2*96 + 81 + t) * 128 + c * 16))) = v;
        }
        __syncthreads();
        gemm3_part(acc3, sbase, j, lane, bb, wm3);
        __syncthreads();
    }

    // ---- board staging: f32 [96][96] per batch over R1 ----
    {
        float* stag = (float*)(sm + (uint32_t)bb * 36864u);
        #pragma unroll
        for (int jb2 = 0; jb2 < 12; ++jb2) {
            int col = jb2*8 + cl, r = wm3*16 + rl;
            stag[r * 96 + col]           = acc3[jb2][0];
            stag[r * 96 + col + 1]       = acc3[jb2][1];
            stag[(r + 8) * 96 + col]     = acc3[jb2][2];
            stag[(r + 8) * 96 + col + 1] = acc3[jb2][3];
        }
    }
    __syncthreads();

    // ---- permuted gather, both batches ----
    {
        float cQK  = __ldg(g_CONST + 0);
        float ckwp = __ldg(g_CONST + 8);
        for (int p = tid; p < 2 * NPOL; p += 384) {
            int bloc = (p >= NPOL);
            int pp = p - bloc * NPOL;
            const float* bs = (const float*)(sm + (uint32_t)bloc * 36864u);
            int r = g_MAP[pp];
            float v;
            if (r < 13122) {
                int rr = (r < 6561) ? r : r - 6561;
                int q = rr / 81, k = rr - q * 81;
                v = bs[q * 96 + k] + bs[90 * 96 + q] + bs[89 * 96 + k] + cQK;
                if (r >= 6561) v += bs[88 * 96 + k] + ckwp;
            } else {
                int r3 = r - 13122;
                int n = r3 / 81, k = r3 - n * 81;
                v = bs[(81 + n) * 96 + k] + __ldg(g_CONST + 1 + n);
            }
            out[(size_t)(blockIdx.x * 2 + bloc) * NPOL + pp] = v;
        }
    }
}

// ---------------- launch ----------------
extern "C" void kernel_launch(void* const* d_in, const int* in_sizes, int n_in,
                              void* d_out, int out_size) {
    const float* x   = (const float*)d_in[0];
    const float* We  = (const float*)d_in[1];
    const float* be  = (const float*)d_in[2];
    const float* Wq  = (const float*)d_in[3];
    const float* bq  = (const float*)d_in[4];
    const float* Wk  = (const float*)d_in[5];
    const float* bk  = (const float*)d_in[6];
    const float* Wp  = (const float*)d_in[7];
    const float* bp  = (const float*)d_in[8];
    const float* dq  = (const float*)d_in[9];
    const void*  raw = d_in[10];
    const void*  pol = d_in[11];
    float* out = (float*)d_out;

    cudaFuncSetAttribute(k_fused, cudaFuncAttributeMaxDynamicSharedMemorySize, SMEM_TOT);

    prep_all<<<529, 256>>>(We, Wq, Wk, Wp, bq, bk, bp, dq, raw, pol);
    k_fused<<<NB / 2, 384, SMEM_TOT>>>(x, be, out);
}

// round 6
// speedup vs baseline: 1.0914x; 1.0914x over previous
#include <cuda_runtime.h>
#include <cuda_fp16.h>
#include <cstdint>

// ---------------- problem constants ----------------
#define NB     4096
#define NPOL   3849
#define NDROP  7
#define SCALE  0.0625f          // 1/sqrt(256)

// ---------------- smem layout (bytes), per CTA (1 batch) ----------------
// R1: X fp16 [96 rows][512B] = 49152 -> later: S_j fp16 [96][128B] @+0 (12288),
//     board f32 [96][96] @+12288 (36864)
// R2: PE fp16 [96 rows][512B] = 49152
// R3: weight chunks, 2 x 8KB ([64 n][64 k] fp16, 128B rows swz128)
#define R1        0u
#define R2        49152u
#define R3        98304u
#define OFF_BOARD 12288u
#define SMEM_TOT  114688u

// ---------------- device scratch ----------------
__device__ __align__(128) __half g_WE  [256*256];   // We^T  [n][k]
__device__ __align__(128) __half g_W2  [256*256];   // SCALE*(Wq Wk^T)^T  [n][k]
__device__ __align__(128) __half g_SEXT[10*256];    // S_ext rows 81..90
__device__ float g_CONST[16];                        // [0]=cQK [1..7]=cdrop [8]=ckwp
__device__ int g_MAP[NPOL];

// ---------------- helpers ----------------
__device__ __forceinline__ uint32_t swz128(uint32_t o) { return o ^ ((o >> 3) & 0x70); }
__device__ __forceinline__ uint32_t swz512(uint32_t o) { return o ^ ((o >> 5) & 0x70); }

__device__ __forceinline__ uint32_t pack2(float a, float b) {
    __half2 h = __floats2half2_rn(a, b);
    return *reinterpret_cast<uint32_t*>(&h);
}

__device__ __forceinline__ void ldsm4(uint32_t& r0, uint32_t& r1, uint32_t& r2, uint32_t& r3, uint32_t addr) {
    asm volatile("ldmatrix.sync.aligned.m8n8.x4.shared.b16 {%0,%1,%2,%3}, [%4];\n"
                 : "=r"(r0), "=r"(r1), "=r"(r2), "=r"(r3) : "r"(addr));
}

__device__ __forceinline__ void ldsm2(uint32_t& r0, uint32_t& r1, uint32_t addr) {
    asm volatile("ldmatrix.sync.aligned.m8n8.x2.shared.b16 {%0,%1}, [%2];\n"
                 : "=r"(r0), "=r"(r1) : "r"(addr));
}

__device__ __forceinline__ void mma16816(float* c, uint32_t a0, uint32_t a1, uint32_t a2, uint32_t a3,
                                         uint32_t b0, uint32_t b1) {
    asm volatile("mma.sync.aligned.m16n8k16.row.col.f32.f16.f16.f32 "
                 "{%0,%1,%2,%3},{%4,%5,%6,%7},{%8,%9},{%0,%1,%2,%3};\n"
                 : "+f"(c[0]), "+f"(c[1]), "+f"(c[2]), "+f"(c[3])
                 : "r"(a0), "r"(a1), "r"(a2), "r"(a3), "r"(b0), "r"(b1));
}

__device__ __forceinline__ float mishf(float v) {
    float e  = __expf(v);
    float sp = (v > 15.f) ? v : __logf(1.f + e);
    float z  = __expf(-2.f * sp);
    float t  = __fdividef(1.f - z, 1.f + z);
    return v * t;
}

__device__ __forceinline__ void cp_async16(uint32_t dst, const void* src) {
    asm volatile("cp.async.cg.shared.global [%0], [%1], 16;\n" :: "r"(dst), "l"(src));
}
__device__ __forceinline__ void cp_commit() { asm volatile("cp.async.commit_group;\n" ::: "memory"); }
template<int N> __device__ __forceinline__ void cp_wait() {
    asm volatile("cp.async.wait_group %0;\n" :: "n"(N) : "memory");
}

// ---------------- unified prep kernel ----------------
__global__ void prep_all(const float* __restrict__ We, const float* __restrict__ Wq,
                         const float* __restrict__ Wk, const float* __restrict__ Wp,
                         const float* __restrict__ bq, const float* __restrict__ bk,
                         const float* __restrict__ bp, const float* __restrict__ dqm,
                         const void* __restrict__ rawp, const void* __restrict__ polp) {
    __shared__ float wkrow[256];
    int bid = blockIdx.x, tid = threadIdx.x;
    int lane = tid & 31, w = tid >> 5;

    if (bid < 256) {
        int n = bid, k = tid;
        g_WE[n*256 + k] = __float2half(We[k*256 + n]);
        wkrow[k] = Wk[n*256 + k];
        __syncthreads();
        const float4* wq = (const float4*)(Wq + (size_t)k * 256);
        float s = 0.f;
        #pragma unroll 8
        for (int o = 0; o < 64; ++o) {
            float4 q = wq[o];
            s += q.x * wkrow[4*o] + q.y * wkrow[4*o+1] + q.z * wkrow[4*o+2] + q.w * wkrow[4*o+3];
        }
        g_W2[n*256 + k] = __float2half(s * SCALE);
    } else if (bid < 512) {
        int j = bid - 256;
        #pragma unroll
        for (int pass = 0; pass < 2; ++pass) {
            int t = (pass == 0) ? w : ((w < 2) ? 8 + w : -1);
            if (t < 0) continue;
            float s = 0.f;
            for (int o = lane; o < 256; o += 32) {
                float term;
                if (t < 7)       term = dqm[t*256 + o] * Wk[j*256 + o];
                else if (t == 7) term = Wk[j*256 + o] * Wp[o];
                else if (t == 8) term = Wk[j*256 + o] * bq[o];
                else             term = Wq[j*256 + o] * bk[o];
                s += term;
            }
            #pragma unroll
            for (int off = 16; off; off >>= 1) s += __shfl_xor_sync(0xffffffffu, s, off);
            if (lane == 0) g_SEXT[t*256 + j] = __float2half((t == 7) ? s : s * SCALE);
        }
    } else if (bid == 512) {
        #pragma unroll
        for (int pass = 0; pass < 2; ++pass) {
            float s = 0.f;
            int which = -1;
            if (pass == 0) {
                if (w == 0) { for (int o = lane; o < 256; o += 32) s += bq[o] * bk[o]; which = 0; }
                else        { for (int o = lane; o < 256; o += 32) s += dqm[(w-1)*256 + o] * bk[o]; which = w; }
            } else if (w == 0) {
                for (int o = lane; o < 256; o += 32) s += bk[o] * Wp[o];
                which = 8;
            }
            if (which < 0) continue;
            #pragma unroll
            for (int off = 16; off; off >>= 1) s += __shfl_xor_sync(0xffffffffu, s, off);
            if (lane == 0) g_CONST[which] = (which == 8) ? (s + bp[0]) : (s * SCALE);
        }
    } else {
        int j = (bid - 513) * 256 + tid;
        if (j < NPOL) {
            const int* r32 = (const int*)rawp;
            bool is64 = (r32[1] == 0 && r32[3] == 0 && r32[5] == 0 && r32[7] == 0);
            long long rv, pv;
            if (is64) { rv = ((const long long*)rawp)[j]; pv = ((const long long*)polp)[j]; }
            else      { rv = r32[j];                      pv = ((const int*)polp)[j]; }
            g_MAP[(int)pv] = (int)rv;
        }
    }
}

// ---------------- fused-kernel building blocks ----------------
// prefetch one [64n][64k] 8KB chunk of W (n-tile j, k-chunk kc) into buffer buf
__device__ __forceinline__ void pf_chunk(uint32_t sbase, const __half* __restrict__ W,
                                         int j, int kc, int buf, int tid) {
    #pragma unroll
    for (int t = 0; t < 2; ++t) {
        int i = tid + t * 256;                 // 512 uint4 sites
        int r = i >> 3, c = i & 7;
        cp_async16(sbase + R3 + (uint32_t)buf * 8192u + swz128((uint32_t)(r * 128 + c * 16)),
                   W + (size_t)(j * 64 + r) * 256 + kc * 64 + c * 8);
    }
    cp_commit();
}

// one [96m x 16n-per-warp x 64k] sub-GEMM; A @ aOff (512B rows swz512), B chunk @ bOff
__device__ __forceinline__ void mma_sub(float acc[3][2][4], uint32_t sbase, uint32_t aOff,
                                        int kc, uint32_t bOff, int lane, int wm, int wn) {
    #pragma unroll
    for (int ks = 0; ks < 4; ++ks) {
        uint32_t a[3][4];
        #pragma unroll
        for (int i = 0; i < 3; ++i) {
            uint32_t off = swz512((uint32_t)((wm*48 + i*16 + (lane & 15)) * 512
                                             + kc*128 + ks*32 + ((lane >> 4) << 4)));
            ldsm4(a[i][0], a[i][1], a[i][2], a[i][3], sbase + aOff + off);
        }
        uint32_t b0, b1, b2, b3;
        uint32_t off = swz128((uint32_t)((wn*16 + (lane & 7) + ((lane >> 4) << 3)) * 128
                                         + ks*32 + (((lane >> 3) & 1) << 4)));
        ldsm4(b0, b1, b2, b3, sbase + bOff + off);
        #pragma unroll
        for (int i = 0; i < 3; ++i) {
            mma16816(acc[i][0], a[i][0], a[i][1], a[i][2], a[i][3], b0, b1);
            mma16816(acc[i][1], a[i][0], a[i][1], a[i][2], a[i][3], b2, b3);
        }
    }
}

// GEMM3 partial for tile j: board += S_j[96][64] * PE[:, 64j..64j+64]^T ; warp tile 48x24
__device__ __forceinline__ void gemm3_part(float acc3[3][3][4], uint32_t sbase, int j,
                                           int lane, int wm, int wn) {
    #pragma unroll
    for (int ks = 0; ks < 4; ++ks) {
        uint32_t a[3][4];
        #pragma unroll
        for (int i = 0; i < 3; ++i) {
            uint32_t off = swz128((uint32_t)((wm*48 + i*16 + (lane & 15)) * 128
                                             + ks*32 + ((lane >> 4) << 4)));
            ldsm4(a[i][0], a[i][1], a[i][2], a[i][3], sbase + R1 + off);
        }
        uint32_t n0 = (uint32_t)(wn * 24);
        uint32_t kbyte = (uint32_t)(j*128 + ks*32);
        uint32_t b0, b1, b2, b3, b4, b5;
        uint32_t off4 = swz512((n0 + (lane & 7) + ((lane >> 4) << 3)) * 512
                               + kbyte + (((lane >> 3) & 1) << 4));
        ldsm4(b0, b1, b2, b3, sbase + R2 + off4);
        uint32_t off2 = swz512((n0 + 16 + (lane & 7)) * 512
                               + kbyte + (((lane >> 3) & 1) << 4));
        ldsm2(b4, b5, sbase + R2 + off2);
        #pragma unroll
        for (int i = 0; i < 3; ++i) {
            mma16816(acc3[i][0], a[i][0], a[i][1], a[i][2], a[i][3], b0, b1);
            mma16816(acc3[i][1], a[i][0], a[i][1], a[i][2], a[i][3], b2, b3);
            mma16816(acc3[i][2], a[i][0], a[i][1], a[i][2], a[i][3], b4, b5);
        }
    }
}

// ---------------- fused kernel: one CTA per batch, 2 CTAs/SM ----------------
__global__ void __launch_bounds__(256, 2) k_fused(const float* __restrict__ X,
                                                  const float* __restrict__ be,
                                                  float* __restrict__ out) {
    extern __shared__ char sm[];
    uint32_t sbase = (uint32_t)__cvta_generic_to_shared(sm);
    int tid = threadIdx.x, lane = tid & 31, w = tid >> 5;
    int wm = w >> 2, wn = w & 3;              // 2m x 4n grids everywhere
    int rl = lane >> 2, cl = (lane & 3) * 2;
    int b = blockIdx.x;

    // ---- chunk0 of We in flight; X (f32->fp16, rows 81-95 zero) into R1 ----
    pf_chunk(sbase, g_WE, 0, 0, 0, tid);
    for (int idx = tid; idx < 3072; idx += 256) {
        int r = idx >> 5, c = idx & 31;
        uint4 u = make_uint4(0u, 0u, 0u, 0u);
        if (r < 81) {
            const float4* p = (const float4*)(X + ((size_t)b * 81 + r) * 256 + c * 8);
            float4 f0 = p[0], f1 = p[1];
            u.x = pack2(f0.x, f0.y); u.y = pack2(f0.z, f0.w);
            u.z = pack2(f1.x, f1.y); u.w = pack2(f1.z, f1.w);
        }
        *(uint4*)(sm + R1 + swz512((uint32_t)(r * 512 + c * 16))) = u;
    }

    // ---- GEMM1: PE = mish(X @ We^T + be) -> R2, n-tiles of 64, k-chunks of 64 ----
    for (int j = 0; j < 4; ++j) {
        float acc[3][2][4] = {};
        #pragma unroll
        for (int kc = 0; kc < 4; ++kc) {
            int u = j * 4 + kc;
            if (u < 15) pf_chunk(sbase, g_WE, (u+1) >> 2, (u+1) & 3, (u+1) & 1, tid);
            else        pf_chunk(sbase, g_W2, 0, 0, 0, tid);   // chain into GEMM2
            cp_wait<1>();
            __syncthreads();
            mma_sub(acc, sbase, R1, kc, R3 + (uint32_t)(u & 1) * 8192u, lane, wm, wn);
            __syncthreads();
        }
        #pragma unroll
        for (int i = 0; i < 3; ++i) {
            int r = wm*48 + i*16 + rl;
            #pragma unroll
            for (int jj = 0; jj < 2; ++jj) {
                int gcol = j*64 + wn*16 + jj*8 + cl;
                float b0 = __ldg(be + gcol), b1 = __ldg(be + gcol + 1);
                *(uint32_t*)(sm + R2 + swz512((uint32_t)(r * 512 + gcol * 2))) =
                    pack2(mishf(acc[i][jj][0] + b0), mishf(acc[i][jj][1] + b1));
                *(uint32_t*)(sm + R2 + swz512((uint32_t)((r + 8) * 512 + gcol * 2))) =
                    pack2(mishf(acc[i][jj][2] + b0), mishf(acc[i][jj][3] + b1));
            }
        }
    }

    // ---- GEMM2 (S n-tiles) fused with GEMM3 (board accumulates in registers) ----
    float acc3[3][3][4] = {};
    for (int j = 0; j < 4; ++j) {
        float acc[3][2][4] = {};
        #pragma unroll
        for (int kc = 0; kc < 4; ++kc) {
            int u = j * 4 + kc;
            if (u < 15) { pf_chunk(sbase, g_W2, (u+1) >> 2, (u+1) & 3, (u+1) & 1, tid); cp_wait<1>(); }
            else        { cp_wait<0>(); }
            __syncthreads();
            mma_sub(acc, sbase, R2, kc, R3 + (uint32_t)(u & 1) * 8192u, lane, wm, wn);
            __syncthreads();
        }
        // S_j epilogue -> fp16 staging @R1 (rows >= 81 come from SEXT/zeros)
        #pragma unroll
        for (int i = 0; i < 3; ++i) {
            int r = wm*48 + i*16 + rl;
            #pragma unroll
            for (int jj = 0; jj < 2; ++jj) {
                int lcol = wn*16 + jj*8 + cl;
                if (r < 81)
                    *(uint32_t*)(sm + R1 + swz128((uint32_t)(r * 128 + lcol * 2))) =
                        pack2(acc[i][jj][0], acc[i][jj][1]);
                if (r + 8 < 81)
                    *(uint32_t*)(sm + R1 + swz128((uint32_t)((r + 8) * 128 + lcol * 2))) =
                        pack2(acc[i][jj][2], acc[i][jj][3]);
            }
        }
        if (tid < 120) {                        // rows 81-90 = SEXT, 91-95 = zeros
            int t = tid >> 3, c = tid & 7;
            uint4 v = make_uint4(0u, 0u, 0u, 0u);
            if (t < 10) v = *(const uint4*)&g_SEXT[t * 256 + j * 64 + c * 8];
            *(uint4*)(sm + R1 + swz128((uint32_t)((81 + t) * 128 + c * 16))) = v;
        }
        __syncthreads();
        gemm3_part(acc3, sbase, j, lane, wm, wn);
        __syncthreads();
    }

    // ---- board staging: f32 [96][96] @ R1+12288 ----
    {
        float* stag = (float*)(sm + OFF_BOARD);
        #pragma unroll
        for (int i = 0; i < 3; ++i) {
            int r = wm*48 + i*16 + rl;
            #pragma unroll
            for (int jj = 0; jj < 3; ++jj) {
                int col = wn*24 + jj*8 + cl;
                stag[r * 96 + col]           = acc3[i][jj][0];
                stag[r * 96 + col + 1]       = acc3[i][jj][1];
                stag[(r + 8) * 96 + col]     = acc3[i][jj][2];
                stag[(r + 8) * 96 + col + 1] = acc3[i][jj][3];
            }
        }
    }
    __syncthreads();

    // ---- permuted gather ----
    {
        const float* bs = (const float*)(sm + OFF_BOARD);
        float cQK  = __ldg(g_CONST + 0);
        float ckwp = __ldg(g_CONST + 8);
        for (int p = tid; p < NPOL; p += 256) {
            int r = g_MAP[p];
            float v;
            if (r < 13122) {
                int rr = (r < 6561) ? r : r - 6561;
                int q = rr / 81, k = rr - q * 81;
                v = bs[q * 96 + k] + bs[90 * 96 + q] + bs[89 * 96 + k] + cQK;
                if (r >= 6561) v += bs[88 * 96 + k] + ckwp;
            } else {
                int r3 = r - 13122;
                int n = r3 / 81, k = r3 - n * 81;
                v = bs[(81 + n) * 96 + k] + __ldg(g_CONST + 1 + n);
            }
            out[(size_t)b * NPOL + p] = v;
        }
    }
}

// ---------------- launch ----------------
extern "C" void kernel_launch(void* const* d_in, const int* in_sizes, int n_in,
                              void* d_out, int out_size) {
    const float* x   = (const float*)d_in[0];
    const float* We  = (const float*)d_in[1];
    const float* be  = (const float*)d_in[2];
    const float* Wq  = (const float*)d_in[3];
    const float* bq  = (const float*)d_in[4];
    const float* Wk  = (const float*)d_in[5];
    const float* bk  = (const float*)d_in[6];
    const float* Wp  = (const float*)d_in[7];
    const float* bp  = (const float*)d_in[8];
    const float* dq  = (const float*)d_in[9];
    const void*  raw = d_in[10];
    const void*  pol = d_in[11];
    float* out = (float*)d_out;

    cudaFuncSetAttribute(k_fused, cudaFuncAttributeMaxDynamicSharedMemorySize, SMEM_TOT);

    prep_all<<<529, 256>>>(We, Wq, Wk, Wp, bq, bk, bp, dq, raw, pol);
    k_fused<<<NB, 256, SMEM_TOT>>>(x, be, out);
}

// round 7
// speedup vs baseline: 1.2453x; 1.1410x over previous
#include <cuda_runtime.h>
#include <cuda_fp16.h>
#include <cstdint>

// ---------------- problem constants ----------------
#define NB     4096
#define NPOL   3849
#define NDROP  7
#define SCALE  0.0625f          // 1/sqrt(256)

// ---------------- smem layout (bytes), per CTA (1 batch), 112KB ----------------
// R1 [0,49152):    X fp16 [96][512B] swz512 during GEMM1
//                  then: S-stage fp16 [96][256B] swz256 @+0 (24KB, per GEMM2 npass)
//                        GEMM2 W-buf1 @+24576 (16KB)
//                  then: board f32 [96][96] @+12288 (36864)
// R2 [49152,98304): PE fp16 col-blocks: block0 (cols 0-127) @+0, block1 @+24576
//                  GEMM1 W-buf1 lives @+24576 until the np1 epilogue
// R3 [98304,114688): W-buf0 (16KB), chunk = [128n][64k] fp16 swz128
#define R1        0u
#define R2        49152u
#define R3        98304u
#define BUFG1     (R2 + 24576u)
#define BUFG2     (R1 + 24576u)
#define OFF_BOARD 12288u
#define SMEM_TOT  114688u

// ---------------- device scratch ----------------
__device__ __align__(128) __half g_WE  [256*256];   // We^T  [n][k]
__device__ __align__(128) __half g_W2  [256*256];   // SCALE*(Wq Wk^T)^T  [n][k]
__device__ __align__(128) __half g_SEXT[10*256];    // S_ext rows 81..90
__device__ float g_CONST[16];                        // [0]=cQK [1..7]=cdrop [8]=ckwp
__device__ int g_MAP[NPOL];

// ---------------- helpers ----------------
__device__ __forceinline__ uint32_t swz128(uint32_t o) { return o ^ ((o >> 3) & 0x70); }
__device__ __forceinline__ uint32_t swz256(uint32_t o) { return o ^ ((o >> 4) & 0x70); }
__device__ __forceinline__ uint32_t swz512(uint32_t o) { return o ^ ((o >> 5) & 0x70); }

__device__ __forceinline__ uint32_t pack2(float a, float b) {
    __half2 h = __floats2half2_rn(a, b);
    return *reinterpret_cast<uint32_t*>(&h);
}

__device__ __forceinline__ void ldsm4(uint32_t& r0, uint32_t& r1, uint32_t& r2, uint32_t& r3, uint32_t addr) {
    asm volatile("ldmatrix.sync.aligned.m8n8.x4.shared.b16 {%0,%1,%2,%3}, [%4];\n"
                 : "=r"(r0), "=r"(r1), "=r"(r2), "=r"(r3) : "r"(addr));
}

__device__ __forceinline__ void ldsm2(uint32_t& r0, uint32_t& r1, uint32_t addr) {
    asm volatile("ldmatrix.sync.aligned.m8n8.x2.shared.b16 {%0,%1}, [%2];\n"
                 : "=r"(r0), "=r"(r1) : "r"(addr));
}

__device__ __forceinline__ void mma16816(float* c, uint32_t a0, uint32_t a1, uint32_t a2, uint32_t a3,
                                         uint32_t b0, uint32_t b1) {
    asm volatile("mma.sync.aligned.m16n8k16.row.col.f32.f16.f16.f32 "
                 "{%0,%1,%2,%3},{%4,%5,%6,%7},{%8,%9},{%0,%1,%2,%3};\n"
                 : "+f"(c[0]), "+f"(c[1]), "+f"(c[2]), "+f"(c[3])
                 : "r"(a0), "r"(a1), "r"(a2), "r"(a3), "r"(b0), "r"(b1));
}

__device__ __forceinline__ float mishf(float v) {
    float e  = __expf(v);
    float sp = (v > 15.f) ? v : __logf(1.f + e);
    float z  = __expf(-2.f * sp);
    float t  = __fdividef(1.f - z, 1.f + z);
    return v * t;
}

__device__ __forceinline__ void cp_async16(uint32_t dst, const void* src) {
    asm volatile("cp.async.cg.shared.global [%0], [%1], 16;\n" :: "r"(dst), "l"(src));
}
__device__ __forceinline__ void cp_commit() { asm volatile("cp.async.commit_group;\n" ::: "memory"); }
template<int N> __device__ __forceinline__ void cp_wait() {
    asm volatile("cp.async.wait_group %0;\n" :: "n"(N) : "memory");
}

// ---------------- unified prep kernel ----------------
__global__ void prep_all(const float* __restrict__ We, const float* __restrict__ Wq,
                         const float* __restrict__ Wk, const float* __restrict__ Wp,
                         const float* __restrict__ bq, const float* __restrict__ bk,
                         const float* __restrict__ bp, const float* __restrict__ dqm,
                         const void* __restrict__ rawp, const void* __restrict__ polp) {
    __shared__ float wkrow[256];
    int bid = blockIdx.x, tid = threadIdx.x;
    int lane = tid & 31, w = tid >> 5;

    if (bid < 256) {
        int n = bid, k = tid;
        g_WE[n*256 + k] = __float2half(We[k*256 + n]);
        wkrow[k] = Wk[n*256 + k];
        __syncthreads();
        const float4* wq = (const float4*)(Wq + (size_t)k * 256);
        float s = 0.f;
        #pragma unroll 8
        for (int o = 0; o < 64; ++o) {
            float4 q = wq[o];
            s += q.x * wkrow[4*o] + q.y * wkrow[4*o+1] + q.z * wkrow[4*o+2] + q.w * wkrow[4*o+3];
        }
        g_W2[n*256 + k] = __float2half(s * SCALE);
    } else if (bid < 512) {
        int j = bid - 256;
        #pragma unroll
        for (int pass = 0; pass < 2; ++pass) {
            int t = (pass == 0) ? w : ((w < 2) ? 8 + w : -1);
            if (t < 0) continue;
            float s = 0.f;
            for (int o = lane; o < 256; o += 32) {
                float term;
                if (t < 7)       term = dqm[t*256 + o] * Wk[j*256 + o];
                else if (t == 7) term = Wk[j*256 + o] * Wp[o];
                else if (t == 8) term = Wk[j*256 + o] * bq[o];
                else             term = Wq[j*256 + o] * bk[o];
                s += term;
            }
            #pragma unroll
            for (int off = 16; off; off >>= 1) s += __shfl_xor_sync(0xffffffffu, s, off);
            if (lane == 0) g_SEXT[t*256 + j] = __float2half((t == 7) ? s : s * SCALE);
        }
    } else if (bid == 512) {
        #pragma unroll
        for (int pass = 0; pass < 2; ++pass) {
            float s = 0.f;
            int which = -1;
            if (pass == 0) {
                if (w == 0) { for (int o = lane; o < 256; o += 32) s += bq[o] * bk[o]; which = 0; }
                else        { for (int o = lane; o < 256; o += 32) s += dqm[(w-1)*256 + o] * bk[o]; which = w; }
            } else if (w == 0) {
                for (int o = lane; o < 256; o += 32) s += bk[o] * Wp[o];
                which = 8;
            }
            if (which < 0) continue;
            #pragma unroll
            for (int off = 16; off; off >>= 1) s += __shfl_xor_sync(0xffffffffu, s, off);
            if (lane == 0) g_CONST[which] = (which == 8) ? (s + bp[0]) : (s * SCALE);
        }
    } else {
        int j = (bid - 513) * 256 + tid;
        if (j < NPOL) {
            const int* r32 = (const int*)rawp;
            bool is64 = (r32[1] == 0 && r32[3] == 0 && r32[5] == 0 && r32[7] == 0);
            long long rv, pv;
            if (is64) { rv = ((const long long*)rawp)[j]; pv = ((const long long*)polp)[j]; }
            else      { rv = r32[j];                      pv = ((const int*)polp)[j]; }
            g_MAP[(int)pv] = (int)rv;
        }
    }
}

// ---------------- fused-kernel building blocks ----------------
// prefetch one [128n][64k] 16KB chunk (n-half np, k-chunk c) to smem address dst
__device__ __forceinline__ void pf16(uint32_t dst, const __half* __restrict__ W,
                                     int np, int c, int tid) {
    #pragma unroll
    for (int t = 0; t < 4; ++t) {
        int i = tid + t * 256;                 // 1024 uint4 sites
        int r = i >> 3, cc = i & 7;
        cp_async16(dst + swz128((uint32_t)(r * 128 + cc * 16)),
                   W + (size_t)(np * 128 + r) * 256 + c * 64 + cc * 8);
    }
    cp_commit();
}

// one [96m x 32n-per-warp x 64k] sub-GEMM. MODE 0: A = X @R1 (swz512);
// MODE 1: A = PE col-blocks @R2 (swz256). c = k-chunk index (0-3).
template<int MODE>
__device__ __forceinline__ void mma_g12(float acc[3][4][4], uint32_t sbase,
                                        int c, uint32_t bOff, int lane, int wm, int wn) {
    #pragma unroll
    for (int ks = 0; ks < 4; ++ks) {
        uint32_t a[3][4];
        #pragma unroll
        for (int i = 0; i < 3; ++i) {
            int row = wm*48 + i*16 + (lane & 15);
            uint32_t addr;
            if (MODE == 0)
                addr = R1 + swz512((uint32_t)(row*512 + c*128 + ks*32 + ((lane >> 4) << 4)));
            else
                addr = R2 + (uint32_t)(c >> 1) * 24576u
                     + swz256((uint32_t)(row*256 + (c & 1)*128 + ks*32 + ((lane >> 4) << 4)));
            ldsm4(a[i][0], a[i][1], a[i][2], a[i][3], sbase + addr);
        }
        #pragma unroll
        for (int jj = 0; jj < 2; ++jj) {
            uint32_t b0, b1, b2, b3;
            uint32_t off = swz128((uint32_t)((wn*32 + jj*16 + (lane & 7) + ((lane >> 4) << 3)) * 128
                                             + ks*32 + (((lane >> 3) & 1) << 4)));
            ldsm4(b0, b1, b2, b3, sbase + bOff + off);
            #pragma unroll
            for (int i = 0; i < 3; ++i) {
                mma16816(acc[i][jj*2],   a[i][0], a[i][1], a[i][2], a[i][3], b0, b1);
                mma16816(acc[i][jj*2+1], a[i][0], a[i][1], a[i][2], a[i][3], b2, b3);
            }
        }
    }
}

// GEMM3 partial for global tile jg: board += S_stage[:, jl*64..][96x64] * PE[:, jg*64..]^T
__device__ __forceinline__ void gemm3_part(float acc3[3][3][4], uint32_t sbase, int jg,
                                           int lane, int wm, int wn) {
    #pragma unroll
    for (int ks = 0; ks < 4; ++ks) {
        uint32_t a[3][4];
        #pragma unroll
        for (int i = 0; i < 3; ++i) {
            int row = wm*48 + i*16 + (lane & 15);
            uint32_t off = swz256((uint32_t)(row*256 + (jg & 1)*128 + ks*32 + ((lane >> 4) << 4)));
            ldsm4(a[i][0], a[i][1], a[i][2], a[i][3], sbase + R1 + off);
        }
        uint32_t n0 = (uint32_t)(wn * 24);
        uint32_t blk = (uint32_t)(jg >> 1) * 24576u;
        uint32_t kb = (uint32_t)((jg & 1) * 128 + ks * 32);
        uint32_t b0, b1, b2, b3, b4, b5;
        uint32_t off4 = swz256((n0 + (lane & 7) + ((lane >> 4) << 3)) * 256
                               + kb + (((lane >> 3) & 1) << 4));
        ldsm4(b0, b1, b2, b3, sbase + R2 + blk + off4);
        uint32_t off2 = swz256((n0 + 16 + (lane & 7)) * 256
                               + kb + (((lane >> 3) & 1) << 4));
        ldsm2(b4, b5, sbase + R2 + blk + off2);
        #pragma unroll
        for (int i = 0; i < 3; ++i) {
            mma16816(acc3[i][0], a[i][0], a[i][1], a[i][2], a[i][3], b0, b1);
            mma16816(acc3[i][1], a[i][0], a[i][1], a[i][2], a[i][3], b2, b3);
            mma16816(acc3[i][2], a[i][0], a[i][1], a[i][2], a[i][3], b4, b5);
        }
    }
}

// ---------------- fused kernel: one CTA per batch, 2 CTAs/SM ----------------
__global__ void __launch_bounds__(256, 2) k_fused(const float* __restrict__ X,
                                                  const float* __restrict__ be,
                                                  float* __restrict__ out) {
    extern __shared__ char sm[];
    uint32_t sbase = (uint32_t)__cvta_generic_to_shared(sm);
    int tid = threadIdx.x, lane = tid & 31, w = tid >> 5;
    int wm = w >> 2, wn = w & 3;              // 2m x 4n grid
    int rl = lane >> 2, cl = (lane & 3) * 2;
    int b = blockIdx.x;

    // ---- GEMM1 chunk0 in flight; X (f32->fp16, rows 81-95 zero) into R1 ----
    pf16(sbase + R3, g_WE, 0, 0, tid);
    for (int idx = tid; idx < 3072; idx += 256) {
        int r = idx >> 5, c = idx & 31;
        uint4 u = make_uint4(0u, 0u, 0u, 0u);
        if (r < 81) {
            const float4* p = (const float4*)(X + ((size_t)b * 81 + r) * 256 + c * 8);
            float4 f0 = p[0], f1 = p[1];
            u.x = pack2(f0.x, f0.y); u.y = pack2(f0.z, f0.w);
            u.z = pack2(f1.x, f1.y); u.w = pack2(f1.z, f1.w);
        }
        *(uint4*)(sm + R1 + swz512((uint32_t)(r * 512 + c * 16))) = u;
    }

    // ---- GEMM1: PE = mish(X @ We^T + be) -> PE col-blocks @R2 ----
    for (int np = 0; np < 2; ++np) {
        float acc[3][4][4] = {};
        #pragma unroll
        for (int kc = 0; kc < 4; ++kc) {
            int u = np * 4 + kc;
            cp_wait<0>();
            __syncthreads();
            if (u < 7) { int v = u + 1; pf16(sbase + ((v & 1) ? BUFG1 : R3), g_WE, v >> 2, v & 3, tid); }
            else       { pf16(sbase + R3, g_W2, 0, 0, tid); }           // chain GEMM2 c0
            mma_g12<0>(acc, sbase, kc, (u & 1) ? BUFG1 : R3, lane, wm, wn);
        }
        if (np == 1) __syncthreads();         // BUFG1 dead before PE block1 overwrites it
        #pragma unroll
        for (int i = 0; i < 3; ++i) {
            int r = wm*48 + i*16 + rl;
            #pragma unroll
            for (int jj = 0; jj < 4; ++jj) {
                int lc = wn*32 + jj*8 + cl;
                int gcol = np*128 + lc;
                float b0 = __ldg(be + gcol), b1 = __ldg(be + gcol + 1);
                uint32_t base = R2 + (uint32_t)np * 24576u;
                *(uint32_t*)(sm + base + swz256((uint32_t)(r * 256 + lc * 2))) =
                    pack2(mishf(acc[i][jj][0] + b0), mishf(acc[i][jj][1] + b1));
                *(uint32_t*)(sm + base + swz256((uint32_t)((r + 8) * 256 + lc * 2))) =
                    pack2(mishf(acc[i][jj][2] + b0), mishf(acc[i][jj][3] + b1));
            }
        }
    }

    // ---- GEMM2 (S n-halves) fused with GEMM3 ----
    pf16(sbase + BUFG2, g_W2, 0, 1, tid);     // X dead; GEMM2 c1
    float acc3[3][3][4] = {};
    for (int np = 0; np < 2; ++np) {
        float acc[3][4][4] = {};
        #pragma unroll
        for (int kc = 0; kc < 4; ++kc) {
            int u = np * 4 + kc;
            cp_wait<0>();
            __syncthreads();
            if (u < 7) { int v = u + 1; pf16(sbase + ((v & 1) ? BUFG2 : R3), g_W2, v >> 2, v & 3, tid); }
            mma_g12<1>(acc, sbase, kc, (u & 1) ? BUFG2 : R3, lane, wm, wn);
        }
        __syncthreads();
        // S-stage epilogue: fp16 [96][256B] swz256 @R1 (rows<81 from acc; 81-95 SEXT/zero)
        #pragma unroll
        for (int i = 0; i < 3; ++i) {
            int r = wm*48 + i*16 + rl;
            #pragma unroll
            for (int jj = 0; jj < 4; ++jj) {
                int lc = wn*32 + jj*8 + cl;
                if (r < 81)
                    *(uint32_t*)(sm + R1 + swz256((uint32_t)(r * 256 + lc * 2))) =
                        pack2(acc[i][jj][0], acc[i][jj][1]);
                if (r + 8 < 81)
                    *(uint32_t*)(sm + R1 + swz256((uint32_t)((r + 8) * 256 + lc * 2))) =
                        pack2(acc[i][jj][2], acc[i][jj][3]);
            }
        }
        if (tid < 240) {                       // rows 81-90 = SEXT cols np*128.., 91-95 zero
            int t = tid >> 4, cc = tid & 15;
            uint4 v = make_uint4(0u, 0u, 0u, 0u);
            if (t < 10) v = *(const uint4*)&g_SEXT[t * 256 + np * 128 + cc * 8];
            *(uint4*)(sm + R1 + swz256((uint32_t)((81 + t) * 256 + cc * 16))) = v;
        }
        __syncthreads();
        gemm3_part(acc3, sbase, np * 2,     lane, wm, wn);
        gemm3_part(acc3, sbase, np * 2 + 1, lane, wm, wn);
    }
    __syncthreads();

    // ---- board staging: f32 [96][96] @ R1+12288 ----
    {
        float* stag = (float*)(sm + OFF_BOARD);
        #pragma unroll
        for (int i = 0; i < 3; ++i) {
            int r = wm*48 + i*16 + rl;
            #pragma unroll
            for (int jb = 0; jb < 3; ++jb) {
                int col = wn*24 + jb*8 + cl;
                stag[r * 96 + col]           = acc3[i][jb][0];
                stag[r * 96 + col + 1]       = acc3[i][jb][1];
                stag[(r + 8) * 96 + col]     = acc3[i][jb][2];
                stag[(r + 8) * 96 + col + 1] = acc3[i][jb][3];
            }
        }
    }
    __syncthreads();

    // ---- permuted gather ----
    {
        const float* bs = (const float*)(sm + OFF_BOARD);
        float cQK  = __ldg(g_CONST + 0);
        float ckwp = __ldg(g_CONST + 8);
        for (int p = tid; p < NPOL; p += 256) {
            int r = g_MAP[p];
            float v;
            if (r < 13122) {
                int rr = (r < 6561) ? r : r - 6561;
                int q = rr / 81, k = rr - q * 81;
                v = bs[q * 96 + k] + bs[90 * 96 + q] + bs[89 * 96 + k] + cQK;
                if (r >= 6561) v += bs[88 * 96 + k] + ckwp;
            } else {
                int r3 = r - 13122;
                int n = r3 / 81, k = r3 - n * 81;
                v = bs[(81 + n) * 96 + k] + __ldg(g_CONST + 1 + n);
            }
            out[(size_t)b * NPOL + p] = v;
        }
    }
}

// ---------------- launch ----------------
extern "C" void kernel_launch(void* const* d_in, const int* in_sizes, int n_in,
                              void* d_out, int out_size) {
    const float* x   = (const float*)d_in[0];
    const float* We  = (const float*)d_in[1];
    const float* be  = (const float*)d_in[2];
    const float* Wq  = (const float*)d_in[3];
    const float* bq  = (const float*)d_in[4];
    const float* Wk  = (const float*)d_in[5];
    const float* bk  = (const float*)d_in[6];
    const float* Wp  = (const float*)d_in[7];
    const float* bp  = (const float*)d_in[8];
    const float* dq  = (const float*)d_in[9];
    const void*  raw = d_in[10];
    const void*  pol = d_in[11];
    float* out = (float*)d_out;

    cudaFuncSetAttribute(k_fused, cudaFuncAttributeMaxDynamicSharedMemorySize, SMEM_TOT);

    prep_all<<<529, 256>>>(We, Wq, Wk, Wp, bq, bk, bp, dq, raw, pol);
    k_fused<<<NB, 256, SMEM_TOT>>>(x, be, out);
}

// round 8
// speedup vs baseline: 1.3454x; 1.0804x over previous
#include <cuda_runtime.h>
#include <cuda_fp16.h>
#include <cstdint>

// ---------------- problem constants ----------------
#define NB     4096
#define NPOL   3849
#define NDROP  7
#define SCALE  0.0625f          // 1/sqrt(256)
#define BST    97               // board staging stride (breaks bank conflicts)

// ---------------- smem layout (bytes), per CTA (1 batch), 112KB ----------------
// R1 [0,49152):    X fp16 [96][512B] swz512 during GEMM1
//                  then: S-stage fp16 [96][256B] swz256 @+0 (24KB, per GEMM2 npass)
//                        GEMM2 W-buf1 @+24576 (16KB)
//                  then: board f32 [96][97] @+12288 (37248B; spills 384B into dead R2)
// R2 [49152,98304): PE fp16 col-blocks: block0 (cols 0-127) @+0, block1 @+24576
//                  GEMM1 W-buf1 lives @+24576 until the np1 epilogue
// R3 [98304,114688): W-buf0 (16KB), chunk = [128n][64k] fp16 swz128
#define R1        0u
#define R2        49152u
#define R3        98304u
#define BUFG1     (R2 + 24576u)
#define BUFG2     (R1 + 24576u)
#define OFF_BOARD 12288u
#define SMEM_TOT  114688u

// ---------------- device scratch ----------------
__device__ __align__(128) __half g_WE  [256*256];   // We^T  [n][k]
__device__ __align__(128) __half g_W2  [256*256];   // SCALE*(Wq Wk^T)^T  [n][k]
__device__ __align__(128) __half g_SEXT[10*256];    // S_ext rows 81..90
__device__ float g_CONST[16];                        // [0]=cQK [1..7]=cdrop [8]=ckwp
__device__ int2 g_MAP2[NPOL];                        // packed gather: offA|offB<<16, offC

// ---------------- helpers ----------------
__device__ __forceinline__ uint32_t swz128(uint32_t o) { return o ^ ((o >> 3) & 0x70); }
__device__ __forceinline__ uint32_t swz256(uint32_t o) { return o ^ ((o >> 4) & 0x70); }
__device__ __forceinline__ uint32_t swz512(uint32_t o) { return o ^ ((o >> 5) & 0x70); }

__device__ __forceinline__ uint32_t pack2(float a, float b) {
    __half2 h = __floats2half2_rn(a, b);
    return *reinterpret_cast<uint32_t*>(&h);
}

__device__ __forceinline__ void ldsm4(uint32_t& r0, uint32_t& r1, uint32_t& r2, uint32_t& r3, uint32_t addr) {
    asm volatile("ldmatrix.sync.aligned.m8n8.x4.shared.b16 {%0,%1,%2,%3}, [%4];\n"
                 : "=r"(r0), "=r"(r1), "=r"(r2), "=r"(r3) : "r"(addr));
}

__device__ __forceinline__ void ldsm2(uint32_t& r0, uint32_t& r1, uint32_t addr) {
    asm volatile("ldmatrix.sync.aligned.m8n8.x2.shared.b16 {%0,%1}, [%2];\n"
                 : "=r"(r0), "=r"(r1) : "r"(addr));
}

__device__ __forceinline__ void mma16816(float* c, uint32_t a0, uint32_t a1, uint32_t a2, uint32_t a3,
                                         uint32_t b0, uint32_t b1) {
    asm volatile("mma.sync.aligned.m16n8k16.row.col.f32.f16.f16.f32 "
                 "{%0,%1,%2,%3},{%4,%5,%6,%7},{%8,%9},{%0,%1,%2,%3};\n"
                 : "+f"(c[0]), "+f"(c[1]), "+f"(c[2]), "+f"(c[3])
                 : "r"(a0), "r"(a1), "r"(a2), "r"(a3), "r"(b0), "r"(b1));
}

// mish(x) = x * (u^2+2u)/(u^2+2u+2), u=e^x  -> 2 MUFU ops, branchless
__device__ __forceinline__ float mishf(float v) {
    float u = __expf(v);
    float d = u * u + 2.f * u + 2.f;
    return v - __fdividef(2.f * v, d);
}

__device__ __forceinline__ void cp_async16(uint32_t dst, const void* src) {
    asm volatile("cp.async.cg.shared.global [%0], [%1], 16;\n" :: "r"(dst), "l"(src));
}
__device__ __forceinline__ void cp_commit() { asm volatile("cp.async.commit_group;\n" ::: "memory"); }
template<int N> __device__ __forceinline__ void cp_wait() {
    asm volatile("cp.async.wait_group %0;\n" :: "n"(N) : "memory");
}

// ---------------- unified prep kernel ----------------
__global__ void prep_all(const float* __restrict__ We, const float* __restrict__ Wq,
                         const float* __restrict__ Wk, const float* __restrict__ Wp,
                         const float* __restrict__ bq, const float* __restrict__ bk,
                         const float* __restrict__ bp, const float* __restrict__ dqm,
                         const void* __restrict__ rawp, const void* __restrict__ polp) {
    __shared__ float wkrow[256];
    int bid = blockIdx.x, tid = threadIdx.x;
    int lane = tid & 31, w = tid >> 5;

    if (bid < 256) {
        int n = bid, k = tid;
        g_WE[n*256 + k] = __float2half(We[k*256 + n]);
        wkrow[k] = Wk[n*256 + k];
        __syncthreads();
        const float4* wq = (const float4*)(Wq + (size_t)k * 256);
        float s = 0.f;
        #pragma unroll 8
        for (int o = 0; o < 64; ++o) {
            float4 q = wq[o];
            s += q.x * wkrow[4*o] + q.y * wkrow[4*o+1] + q.z * wkrow[4*o+2] + q.w * wkrow[4*o+3];
        }
        g_W2[n*256 + k] = __float2half(s * SCALE);
    } else if (bid < 512) {
        int j = bid - 256;
        #pragma unroll
        for (int pass = 0; pass < 2; ++pass) {
            int t = (pass == 0) ? w : ((w < 2) ? 8 + w : -1);
            if (t < 0) continue;
            float s = 0.f;
            for (int o = lane; o < 256; o += 32) {
                float term;
                if (t < 7)       term = dqm[t*256 + o] * Wk[j*256 + o];
                else if (t == 7) term = Wk[j*256 + o] * Wp[o];
                else if (t == 8) term = Wk[j*256 + o] * bq[o];
                else             term = Wq[j*256 + o] * bk[o];
                s += term;
            }
            #pragma unroll
            for (int off = 16; off; off >>= 1) s += __shfl_xor_sync(0xffffffffu, s, off);
            if (lane == 0) g_SEXT[t*256 + j] = __float2half((t == 7) ? s : s * SCALE);
        }
    } else if (bid == 512) {
        #pragma unroll
        for (int pass = 0; pass < 2; ++pass) {
            float s = 0.f;
            int which = -1;
            if (pass == 0) {
                if (w == 0) { for (int o = lane; o < 256; o += 32) s += bq[o] * bk[o]; which = 0; }
                else        { for (int o = lane; o < 256; o += 32) s += dqm[(w-1)*256 + o] * bk[o]; which = w; }
            } else if (w == 0) {
                for (int o = lane; o < 256; o += 32) s += bk[o] * Wp[o];
                which = 8;
            }
            if (which < 0) continue;
            #pragma unroll
            for (int off = 16; off; off >>= 1) s += __shfl_xor_sync(0xffffffffu, s, off);
            if (lane == 0) g_CONST[which] = (which == 8) ? (s + bp[0]) : (s * SCALE);
        }
    } else {
        int j = (bid - 513) * 256 + tid;
        if (j < NPOL) {
            const int* r32 = (const int*)rawp;
            bool is64 = (r32[1] == 0 && r32[3] == 0 && r32[5] == 0 && r32[7] == 0);
            long long rv, pv;
            if (is64) { rv = ((const long long*)rawp)[j]; pv = ((const long long*)polp)[j]; }
            else      { rv = r32[j];                      pv = ((const int*)polp)[j]; }
            int r = (int)rv;
            int offA, offB, offC;
            if (r < 13122) {
                int rr = (r < 6561) ? r : r - 6561;
                int q = rr / 81, k = rr - q * 81;
                offA = q * BST + k;
                offB = 90 * BST + q;                               // u[q] + cQK (fixed up)
                offC = (r < 6561) ? (89 * BST + k)                 // v[k]
                                  : (91 * BST + k);                // v[k]+kwp'[k] (fixed up)
            } else {
                int r3 = r - 13122;
                int n = r3 / 81, k = r3 - n * 81;
                offA = (81 + n) * BST + k;                         // drop (+cdrop fixed up)
                offB = 92 * BST;                                   // zero cell
                offC = 92 * BST;
            }
            g_MAP2[(int)pv] = make_int2(offA | (offB << 16), offC);
        }
    }
}

// ---------------- fused-kernel building blocks ----------------
// prefetch one [128n][64k] 16KB chunk (n-half np, k-chunk c) to smem address dst
__device__ __forceinline__ void pf16(uint32_t dst, const __half* __restrict__ W,
                                     int np, int c, int tid) {
    #pragma unroll
    for (int t = 0; t < 4; ++t) {
        int i = tid + t * 256;                 // 1024 uint4 sites
        int r = i >> 3, cc = i & 7;
        cp_async16(dst + swz128((uint32_t)(r * 128 + cc * 16)),
                   W + (size_t)(np * 128 + r) * 256 + c * 64 + cc * 8);
    }
    cp_commit();
}

// one [96m x 32n-per-warp x 64k] sub-GEMM. MODE 0: A = X @R1 (swz512);
// MODE 1: A = PE col-blocks @R2 (swz256). c = k-chunk index (0-3).
template<int MODE>
__device__ __forceinline__ void mma_g12(float acc[3][4][4], uint32_t sbase,
                                        int c, uint32_t bOff, int lane, int wm, int wn) {
    #pragma unroll
    for (int ks = 0; ks < 4; ++ks) {
        uint32_t a[3][4];
        #pragma unroll
        for (int i = 0; i < 3; ++i) {
            int row = wm*48 + i*16 + (lane & 15);
            uint32_t addr;
            if (MODE == 0)
                addr = R1 + swz512((uint32_t)(row*512 + c*128 + ks*32 + ((lane >> 4) << 4)));
            else
                addr = R2 + (uint32_t)(c >> 1) * 24576u
                     + swz256((uint32_t)(row*256 + (c & 1)*128 + ks*32 + ((lane >> 4) << 4)));
            ldsm4(a[i][0], a[i][1], a[i][2], a[i][3], sbase + addr);
        }
        #pragma unroll
        for (int jj = 0; jj < 2; ++jj) {
            uint32_t b0, b1, b2, b3;
            uint32_t off = swz128((uint32_t)((wn*32 + jj*16 + (lane & 7) + ((lane >> 4) << 3)) * 128
                                             + ks*32 + (((lane >> 3) & 1) << 4)));
            ldsm4(b0, b1, b2, b3, sbase + bOff + off);
            #pragma unroll
            for (int i = 0; i < 3; ++i) {
                mma16816(acc[i][jj*2],   a[i][0], a[i][1], a[i][2], a[i][3], b0, b1);
                mma16816(acc[i][jj*2+1], a[i][0], a[i][1], a[i][2], a[i][3], b2, b3);
            }
        }
    }
}

// GEMM3 partial for global tile jg: board += S_stage[:, jl*64..][96x64] * PE[:, jg*64..]^T
__device__ __forceinline__ void gemm3_part(float acc3[3][3][4], uint32_t sbase, int jg,
                                           int lane, int wm, int wn) {
    #pragma unroll
    for (int ks = 0; ks < 4; ++ks) {
        uint32_t a[3][4];
        #pragma unroll
        for (int i = 0; i < 3; ++i) {
            int row = wm*48 + i*16 + (lane & 15);
            uint32_t off = swz256((uint32_t)(row*256 + (jg & 1)*128 + ks*32 + ((lane >> 4) << 4)));
            ldsm4(a[i][0], a[i][1], a[i][2], a[i][3], sbase + R1 + off);
        }
        uint32_t n0 = (uint32_t)(wn * 24);
        uint32_t blk = (uint32_t)(jg >> 1) * 24576u;
        uint32_t kb = (uint32_t)((jg & 1) * 128 + ks * 32);
        uint32_t b0, b1, b2, b3, b4, b5;
        uint32_t off4 = swz256((n0 + (lane & 7) + ((lane >> 4) << 3)) * 256
                               + kb + (((lane >> 3) & 1) << 4));
        ldsm4(b0, b1, b2, b3, sbase + R2 + blk + off4);
        uint32_t off2 = swz256((n0 + 16 + (lane & 7)) * 256
                               + kb + (((lane >> 3) & 1) << 4));
        ldsm2(b4, b5, sbase + R2 + blk + off2);
        #pragma unroll
        for (int i = 0; i < 3; ++i) {
            mma16816(acc3[i][0], a[i][0], a[i][1], a[i][2], a[i][3], b0, b1);
            mma16816(acc3[i][1], a[i][0], a[i][1], a[i][2], a[i][3], b2, b3);
            mma16816(acc3[i][2], a[i][0], a[i][1], a[i][2], a[i][3], b4, b5);
        }
    }
}

// ---------------- fused kernel: one CTA per batch, 2 CTAs/SM ----------------
__global__ void __launch_bounds__(256, 2) k_fused(const float* __restrict__ X,
                                                  const float* __restrict__ be,
                                                  float* __restrict__ out) {
    extern __shared__ char sm[];
    uint32_t sbase = (uint32_t)__cvta_generic_to_shared(sm);
    int tid = threadIdx.x, lane = tid & 31, w = tid >> 5;
    int wm = w >> 2, wn = w & 3;              // 2m x 4n grid
    int rl = lane >> 2, cl = (lane & 3) * 2;
    int b = blockIdx.x;

    // ---- GEMM1 chunk0 in flight; X (f32->fp16, rows 81-95 zero) into R1 ----
    pf16(sbase + R3, g_WE, 0, 0, tid);
    for (int idx = tid; idx < 3072; idx += 256) {
        int r = idx >> 5, c = idx & 31;
        uint4 u = make_uint4(0u, 0u, 0u, 0u);
        if (r < 81) {
            const float4* p = (const float4*)(X + ((size_t)b * 81 + r) * 256 + c * 8);
            float4 f0 = p[0], f1 = p[1];
            u.x = pack2(f0.x, f0.y); u.y = pack2(f0.z, f0.w);
            u.z = pack2(f1.x, f1.y); u.w = pack2(f1.z, f1.w);
        }
        *(uint4*)(sm + R1 + swz512((uint32_t)(r * 512 + c * 16))) = u;
    }

    // ---- GEMM1: PE = mish(X @ We^T + be) -> PE col-blocks @R2 (rows>=81 zeroed) ----
    for (int np = 0; np < 2; ++np) {
        float acc[3][4][4] = {};
        #pragma unroll
        for (int kc = 0; kc < 4; ++kc) {
            int u = np * 4 + kc;
            cp_wait<0>();
            __syncthreads();
            if (u < 7) { int v = u + 1; pf16(sbase + ((v & 1) ? BUFG1 : R3), g_WE, v >> 2, v & 3, tid); }
            else       { pf16(sbase + R3, g_W2, 0, 0, tid); }           // chain GEMM2 c0
            mma_g12<0>(acc, sbase, kc, (u & 1) ? BUFG1 : R3, lane, wm, wn);
        }
        if (np == 1) __syncthreads();         // BUFG1 dead before PE block1 overwrites it
        #pragma unroll
        for (int i = 0; i < 3; ++i) {
            int r = wm*48 + i*16 + rl;
            #pragma unroll
            for (int jj = 0; jj < 4; ++jj) {
                int lc = wn*32 + jj*8 + cl;
                int gcol = np*128 + lc;
                float b0 = __ldg(be + gcol), b1 = __ldg(be + gcol + 1);
                uint32_t base = R2 + (uint32_t)np * 24576u;
                uint32_t w0 = 0u, w1 = 0u;
                if (r < 81)
                    w0 = pack2(mishf(acc[i][jj][0] + b0), mishf(acc[i][jj][1] + b1));
                if (r + 8 < 81)
                    w1 = pack2(mishf(acc[i][jj][2] + b0), mishf(acc[i][jj][3] + b1));
                *(uint32_t*)(sm + base + swz256((uint32_t)(r * 256 + lc * 2))) = w0;
                *(uint32_t*)(sm + base + swz256((uint32_t)((r + 8) * 256 + lc * 2))) = w1;
            }
        }
    }

    // ---- GEMM2 (S n-halves) fused with GEMM3 ----
    pf16(sbase + BUFG2, g_W2, 0, 1, tid);     // X dead; GEMM2 c1
    float acc3[3][3][4] = {};
    for (int np = 0; np < 2; ++np) {
        float acc[3][4][4] = {};
        #pragma unroll
        for (int kc = 0; kc < 4; ++kc) {
            int u = np * 4 + kc;
            cp_wait<0>();
            __syncthreads();
            if (u < 7) { int v = u + 1; pf16(sbase + ((v & 1) ? BUFG2 : R3), g_W2, v >> 2, v & 3, tid); }
            mma_g12<1>(acc, sbase, kc, (u & 1) ? BUFG2 : R3, lane, wm, wn);
        }
        __syncthreads();
        // S-stage epilogue: fp16 [96][256B] swz256 @R1 (rows<81 from acc; 81-95 SEXT/zero)
        #pragma unroll
        for (int i = 0; i < 3; ++i) {
            int r = wm*48 + i*16 + rl;
            #pragma unroll
            for (int jj = 0; jj < 4; ++jj) {
                int lc = wn*32 + jj*8 + cl;
                if (r < 81)
                    *(uint32_t*)(sm + R1 + swz256((uint32_t)(r * 256 + lc * 2))) =
                        pack2(acc[i][jj][0], acc[i][jj][1]);
                if (r + 8 < 81)
                    *(uint32_t*)(sm + R1 + swz256((uint32_t)((r + 8) * 256 + lc * 2))) =
                        pack2(acc[i][jj][2], acc[i][jj][3]);
            }
        }
        if (tid < 240) {                       // rows 81-90 = SEXT cols np*128.., 91-95 zero
            int t = tid >> 4, cc = tid & 15;
            uint4 v = make_uint4(0u, 0u, 0u, 0u);
            if (t < 10) v = *(const uint4*)&g_SEXT[t * 256 + np * 128 + cc * 8];
            *(uint4*)(sm + R1 + swz256((uint32_t)((81 + t) * 256 + cc * 16))) = v;
        }
        __syncthreads();
        gemm3_part(acc3, sbase, np * 2,     lane, wm, wn);
        gemm3_part(acc3, sbase, np * 2 + 1, lane, wm, wn);
    }
    __syncthreads();

    // ---- board staging: f32 [96][BST] @ R1+12288 (conflict-free stride) ----
    {
        float* stag = (float*)(sm + OFF_BOARD);
        #pragma unroll
        for (int i = 0; i < 3; ++i) {
            int r = wm*48 + i*16 + rl;
            #pragma unroll
            for (int jb = 0; jb < 3; ++jb) {
                int col = wn*24 + jb*8 + cl;
                stag[r * BST + col]           = acc3[i][jb][0];
                stag[r * BST + col + 1]       = acc3[i][jb][1];
                stag[(r + 8) * BST + col]     = acc3[i][jb][2];
                stag[(r + 8) * BST + col + 1] = acc3[i][jb][3];
            }
        }
    }
    __syncthreads();

    // ---- fixups: fold constants into aux rows (row90+=cQK; row91=row89+row88+ckwp;
    //      drop rows += cdrop[n]). Rows 92-95 stay exactly zero (zero cell). ----
    {
        float* bs = (float*)(sm + OFF_BOARD);
        float cQK  = g_CONST[0];
        float ckwp = g_CONST[8];
        for (int t = tid; t < 729; t += 256) {
            if (t < 81)       bs[90 * BST + t] += cQK;
            else if (t < 162) { int k = t - 81; bs[91 * BST + k] = bs[89 * BST + k] + bs[88 * BST + k] + ckwp; }
            else              { int u2 = t - 162; int n = u2 / 81, k = u2 - n * 81;
                                bs[(81 + n) * BST + k] += g_CONST[1 + n]; }
        }
    }
    __syncthreads();

    // ---- permuted gather: branchless 3-address form ----
    {
        const float* bs = (const float*)(sm + OFF_BOARD);
        for (int p = tid; p < NPOL; p += 256) {
            int2 m = g_MAP2[p];
            int offA = m.x & 0xffff, offB = m.x >> 16;
            out[(size_t)b * NPOL + p] = bs[offA] + bs[offB] + bs[m.y];
        }
    }
}

// ---------------- launch ----------------
extern "C" void kernel_launch(void* const* d_in, const int* in_sizes, int n_in,
                              void* d_out, int out_size) {
    const float* x   = (const float*)d_in[0];
    const float* We  = (const float*)d_in[1];
    const float* be  = (const float*)d_in[2];
    const float* Wq  = (const float*)d_in[3];
    const float* bq  = (const float*)d_in[4];
    const float* Wk  = (const float*)d_in[5];
    const float* bk  = (const float*)d_in[6];
    const float* Wp  = (const float*)d_in[7];
    const float* bp  = (const float*)d_in[8];
    const float* dq  = (const float*)d_in[9];
    const void*  raw = d_in[10];
    const void*  pol = d_in[11];
    float* out = (float*)d_out;

    cudaFuncSetAttribute(k_fused, cudaFuncAttributeMaxDynamicSharedMemorySize, SMEM_TOT);

    prep_all<<<529, 256>>>(We, Wq, Wk, Wp, bq, bk, bp, dq, raw, pol);
    k_fused<<<NB, 256, SMEM_TOT>>>(x, be, out);
}

// round 9
// speedup vs baseline: 1.4869x; 1.1051x over previous
#include <cuda_runtime.h>
#include <cuda_fp16.h>
#include <cstdint>

// ---------------- problem constants ----------------
#define NB     4096
#define NPOL   3849
#define NDROP  7
#define SCALE  0.0625f          // 1/sqrt(256)
#define BST    97               // board staging stride (breaks bank conflicts)

// ---------------- smem layout (bytes), per CTA (1 batch), 112KB ----------------
#define R1        0u
#define R2        49152u
#define R3        98304u
#define BUFG1     (R2 + 24576u)
#define BUFG2     (R1 + 24576u)
#define OFF_BOARD 12288u
#define SMEM_TOT  114688u

// ---------------- device scratch ----------------
__device__ __align__(128) __half g_WE  [256*256];   // We^T  [n][k]
__device__ __align__(128) __half g_W2  [256*256];   // SCALE*(Wq Wk^T)^T  [n][k]
__device__ __align__(128) __half g_SEXT[10*256];    // S_ext rows 81..90
__device__ float g_CONST[16];                        // [0]=cQK [1..7]=cdrop [8]=ckwp
__device__ __align__(16) int2 g_MAP2[NPOL + 1];      // packed gather: offA|offB<<16, offC

// ---------------- helpers ----------------
__device__ __forceinline__ uint32_t swz128(uint32_t o) { return o ^ ((o >> 3) & 0x70); }
__device__ __forceinline__ uint32_t swz256(uint32_t o) { return o ^ ((o >> 4) & 0x70); }
__device__ __forceinline__ uint32_t swz512(uint32_t o) { return o ^ ((o >> 5) & 0x70); }

__device__ __forceinline__ uint32_t pack2(float a, float b) {
    __half2 h = __floats2half2_rn(a, b);
    return *reinterpret_cast<uint32_t*>(&h);
}

__device__ __forceinline__ void ldsm4(uint32_t& r0, uint32_t& r1, uint32_t& r2, uint32_t& r3, uint32_t addr) {
    asm volatile("ldmatrix.sync.aligned.m8n8.x4.shared.b16 {%0,%1,%2,%3}, [%4];\n"
                 : "=r"(r0), "=r"(r1), "=r"(r2), "=r"(r3) : "r"(addr));
}

__device__ __forceinline__ void ldsm2(uint32_t& r0, uint32_t& r1, uint32_t addr) {
    asm volatile("ldmatrix.sync.aligned.m8n8.x2.shared.b16 {%0,%1}, [%2];\n"
                 : "=r"(r0), "=r"(r1) : "r"(addr));
}

__device__ __forceinline__ void mma16816(float* c, uint32_t a0, uint32_t a1, uint32_t a2, uint32_t a3,
                                         uint32_t b0, uint32_t b1) {
    asm volatile("mma.sync.aligned.m16n8k16.row.col.f32.f16.f16.f32 "
                 "{%0,%1,%2,%3},{%4,%5,%6,%7},{%8,%9},{%0,%1,%2,%3};\n"
                 : "+f"(c[0]), "+f"(c[1]), "+f"(c[2]), "+f"(c[3])
                 : "r"(a0), "r"(a1), "r"(a2), "r"(a3), "r"(b0), "r"(b1));
}

// mish(x) = x - 2x/(u^2+2u+2), u=e^x  -> 2 MUFU ops, branchless
__device__ __forceinline__ float mishf(float v) {
    float u = __expf(v);
    float d = u * u + 2.f * u + 2.f;
    return v - __fdividef(2.f * v, d);
}

__device__ __forceinline__ void cp_async16(uint32_t dst, const void* src) {
    asm volatile("cp.async.cg.shared.global [%0], [%1], 16;\n" :: "r"(dst), "l"(src));
}
__device__ __forceinline__ void cp_commit() { asm volatile("cp.async.commit_group;\n" ::: "memory"); }
template<int N> __device__ __forceinline__ void cp_wait() {
    asm volatile("cp.async.wait_group %0;\n" :: "n"(N) : "memory");
}

// ---------------- unified prep kernel ----------------
__global__ void prep_all(const float* __restrict__ We, const float* __restrict__ Wq,
                         const float* __restrict__ Wk, const float* __restrict__ Wp,
                         const float* __restrict__ bq, const float* __restrict__ bk,
                         const float* __restrict__ bp, const float* __restrict__ dqm,
                         const void* __restrict__ rawp, const void* __restrict__ polp) {
    __shared__ float wkrow[256];
    int bid = blockIdx.x, tid = threadIdx.x;
    int lane = tid & 31, w = tid >> 5;

    if (bid < 256) {
        int n = bid, k = tid;
        g_WE[n*256 + k] = __float2half(We[k*256 + n]);
        wkrow[k] = Wk[n*256 + k];
        __syncthreads();
        const float4* wq = (const float4*)(Wq + (size_t)k * 256);
        float s = 0.f;
        #pragma unroll 8
        for (int o = 0; o < 64; ++o) {
            float4 q = wq[o];
            s += q.x * wkrow[4*o] + q.y * wkrow[4*o+1] + q.z * wkrow[4*o+2] + q.w * wkrow[4*o+3];
        }
        g_W2[n*256 + k] = __float2half(s * SCALE);
    } else if (bid < 512) {
        int j = bid - 256;
        #pragma unroll
        for (int pass = 0; pass < 2; ++pass) {
            int t = (pass == 0) ? w : ((w < 2) ? 8 + w : -1);
            if (t < 0) continue;
            float s = 0.f;
            for (int o = lane; o < 256; o += 32) {
                float term;
                if (t < 7)       term = dqm[t*256 + o] * Wk[j*256 + o];
                else if (t == 7) term = Wk[j*256 + o] * Wp[o];
                else if (t == 8) term = Wk[j*256 + o] * bq[o];
                else             term = Wq[j*256 + o] * bk[o];
                s += term;
            }
            #pragma unroll
            for (int off = 16; off; off >>= 1) s += __shfl_xor_sync(0xffffffffu, s, off);
            if (lane == 0) g_SEXT[t*256 + j] = __float2half((t == 7) ? s : s * SCALE);
        }
    } else if (bid == 512) {
        #pragma unroll
        for (int pass = 0; pass < 2; ++pass) {
            float s = 0.f;
            int which = -1;
            if (pass == 0) {
                if (w == 0) { for (int o = lane; o < 256; o += 32) s += bq[o] * bk[o]; which = 0; }
                else        { for (int o = lane; o < 256; o += 32) s += dqm[(w-1)*256 + o] * bk[o]; which = w; }
            } else if (w == 0) {
                for (int o = lane; o < 256; o += 32) s += bk[o] * Wp[o];
                which = 8;
            }
            if (which < 0) continue;
            #pragma unroll
            for (int off = 16; off; off >>= 1) s += __shfl_xor_sync(0xffffffffu, s, off);
            if (lane == 0) g_CONST[which] = (which == 8) ? (s + bp[0]) : (s * SCALE);
        }
        if (tid == 0) g_MAP2[NPOL] = make_int2(92 * BST, 92 * BST);   // pad slot -> zero cell
    } else {
        int j = (bid - 513) * 256 + tid;
        if (j < NPOL) {
            const int* r32 = (const int*)rawp;
            bool is64 = (r32[1] == 0 && r32[3] == 0 && r32[5] == 0 && r32[7] == 0);
            long long rv, pv;
            if (is64) { rv = ((const long long*)rawp)[j]; pv = ((const long long*)polp)[j]; }
            else      { rv = r32[j];                      pv = ((const int*)polp)[j]; }
            int r = (int)rv;
            int offA, offB, offC;
            if (r < 13122) {
                int rr = (r < 6561) ? r : r - 6561;
                int q = rr / 81, k = rr - q * 81;
                offA = q * BST + k;
                offB = 90 * BST + q;
                offC = (r < 6561) ? (89 * BST + k) : (91 * BST + k);
            } else {
                int r3 = r - 13122;
                int n = r3 / 81, k = r3 - n * 81;
                offA = (81 + n) * BST + k;
                offB = 92 * BST;
                offC = 92 * BST;
            }
            g_MAP2[(int)pv] = make_int2(offA | (offB << 16), offC);
        }
    }
}

// ---------------- fused-kernel building blocks ----------------
__device__ __forceinline__ void pf16(uint32_t dst, const __half* __restrict__ W,
                                     int np, int c, int tid) {
    #pragma unroll
    for (int t = 0; t < 4; ++t) {
        int i = tid + t * 256;
        int r = i >> 3, cc = i & 7;
        cp_async16(dst + swz128((uint32_t)(r * 128 + cc * 16)),
                   W + (size_t)(np * 128 + r) * 256 + c * 64 + cc * 8);
    }
    cp_commit();
}

// one [96m x 32n-per-warp x 64k] sub-GEMM, XOR-hoisted addressing.
// MODE 0: A = X @R1 (swz512); MODE 1: A = PE col-blocks @R2 (swz256).
template<int MODE>
__device__ __forceinline__ void mma_g12(float acc[3][4][4], uint32_t sbase,
                                        int c, uint32_t bOff, int lane, int wm, int wn) {
    // hoisted base addresses: ks-dependent part is pure XOR (ks*32 never carries)
    uint32_t aBase[3], bBase[2];
    #pragma unroll
    for (int i = 0; i < 3; ++i) {
        int row = wm*48 + i*16 + (lane & 15);
        if (MODE == 0)
            aBase[i] = sbase + R1 + swz512((uint32_t)(row*512 + c*128 + ((lane >> 4) << 4)));
        else
            aBase[i] = sbase + R2 + (uint32_t)(c >> 1) * 24576u
                     + swz256((uint32_t)(row*256 + (c & 1)*128 + ((lane >> 4) << 4)));
    }
    #pragma unroll
    for (int jj = 0; jj < 2; ++jj)
        bBase[jj] = sbase + bOff
                  + swz128((uint32_t)((wn*32 + jj*16 + (lane & 7) + ((lane >> 4) << 3)) * 128
                                      + (((lane >> 3) & 1) << 4)));
    #pragma unroll
    for (int ks = 0; ks < 4; ++ks) {
        uint32_t kx = (uint32_t)(ks << 5);
        uint32_t a[3][4];
        #pragma unroll
        for (int i = 0; i < 3; ++i)
            ldsm4(a[i][0], a[i][1], a[i][2], a[i][3], aBase[i] ^ kx);
        #pragma unroll
        for (int jj = 0; jj < 2; ++jj) {
            uint32_t b0, b1, b2, b3;
            ldsm4(b0, b1, b2, b3, bBase[jj] ^ kx);
            #pragma unroll
            for (int i = 0; i < 3; ++i) {
                mma16816(acc[i][jj*2],   a[i][0], a[i][1], a[i][2], a[i][3], b0, b1);
                mma16816(acc[i][jj*2+1], a[i][0], a[i][1], a[i][2], a[i][3], b2, b3);
            }
        }
    }
}

// GEMM3 partial for global tile jg: board += S_stage[:, local 64k] * PE[:, jg*64..]^T
__device__ __forceinline__ void gemm3_part(float acc3[3][3][4], uint32_t sbase, int jg,
                                           int lane, int wm, int wn) {
    uint32_t aBase[3];
    #pragma unroll
    for (int i = 0; i < 3; ++i) {
        int row = wm*48 + i*16 + (lane & 15);
        aBase[i] = sbase + R1 + swz256((uint32_t)(row*256 + (jg & 1)*128 + ((lane >> 4) << 4)));
    }
    uint32_t n0 = (uint32_t)(wn * 24);
    uint32_t blk = sbase + R2 + (uint32_t)(jg >> 1) * 24576u;
    uint32_t kb = (uint32_t)((jg & 1) * 128);
    uint32_t b4Base = blk + swz256((n0 + (lane & 7) + ((lane >> 4) << 3)) * 256
                                   + kb + (((lane >> 3) & 1) << 4));
    uint32_t b2Base = blk + swz256((n0 + 16 + (lane & 7)) * 256
                                   + kb + (((lane >> 3) & 1) << 4));
    #pragma unroll
    for (int ks = 0; ks < 4; ++ks) {
        uint32_t kx = (uint32_t)(ks << 5);
        uint32_t a[3][4];
        #pragma unroll
        for (int i = 0; i < 3; ++i)
            ldsm4(a[i][0], a[i][1], a[i][2], a[i][3], aBase[i] ^ kx);
        uint32_t b0, b1, b2, b3, b4, b5;
        ldsm4(b0, b1, b2, b3, b4Base ^ kx);
        ldsm2(b4, b5, b2Base ^ kx);
        #pragma unroll
        for (int i = 0; i < 3; ++i) {
            mma16816(acc3[i][0], a[i][0], a[i][1], a[i][2], a[i][3], b0, b1);
            mma16816(acc3[i][1], a[i][0], a[i][1], a[i][2], a[i][3], b2, b3);
            mma16816(acc3[i][2], a[i][0], a[i][1], a[i][2], a[i][3], b4, b5);
        }
    }
}

// ---------------- fused kernel: one CTA per batch, 2 CTAs/SM ----------------
__global__ void __launch_bounds__(256, 2) k_fused(const float* __restrict__ X,
                                                  const float* __restrict__ be,
                                                  float* __restrict__ out) {
    extern __shared__ char sm[];
    uint32_t sbase = (uint32_t)__cvta_generic_to_shared(sm);
    int tid = threadIdx.x, lane = tid & 31, w = tid >> 5;
    int wm = w >> 2, wn = w & 3;              // 2m x 4n grid
    int rl = lane >> 2, cl = (lane & 3) * 2;
    int b = blockIdx.x;

    // ---- GEMM1 chunk0 in flight; X (f32->fp16, rows 81-95 zero) into R1 ----
    pf16(sbase + R3, g_WE, 0, 0, tid);
    for (int idx = tid; idx < 3072; idx += 256) {
        int r = idx >> 5, c = idx & 31;
        uint4 u = make_uint4(0u, 0u, 0u, 0u);
        if (r < 81) {
            const float4* p = (const float4*)(X + ((size_t)b * 81 + r) * 256 + c * 8);
            float4 f0 = p[0], f1 = p[1];
            u.x = pack2(f0.x, f0.y); u.y = pack2(f0.z, f0.w);
            u.z = pack2(f1.x, f1.y); u.w = pack2(f1.z, f1.w);
        }
        *(uint4*)(sm + R1 + swz512((uint32_t)(r * 512 + c * 16))) = u;
    }

    // ---- preload bias into registers (epilogue columns fixed per thread) ----
    float2 biasv[2][4];
    #pragma unroll
    for (int np = 0; np < 2; ++np)
        #pragma unroll
        for (int jj = 0; jj < 4; ++jj)
            biasv[np][jj] = *(const float2*)(be + np*128 + wn*32 + jj*8 + cl);

    // ---- GEMM1: PE = mish(X @ We^T + be) -> PE col-blocks @R2 (rows>=81 zeroed) ----
    for (int np = 0; np < 2; ++np) {
        float acc[3][4][4] = {};
        #pragma unroll
        for (int kc = 0; kc < 4; ++kc) {
            int u = np * 4 + kc;
            cp_wait<0>();
            __syncthreads();
            if (u < 7) { int v = u + 1; pf16(sbase + ((v & 1) ? BUFG1 : R3), g_WE, v >> 2, v & 3, tid); }
            else       { pf16(sbase + R3, g_W2, 0, 0, tid); }           // chain GEMM2 c0
            mma_g12<0>(acc, sbase, kc, (u & 1) ? BUFG1 : R3, lane, wm, wn);
        }
        if (np == 1) __syncthreads();         // BUFG1 dead before PE block1 overwrites it
        #pragma unroll
        for (int i = 0; i < 3; ++i) {
            int r = wm*48 + i*16 + rl;
            #pragma unroll
            for (int jj = 0; jj < 4; ++jj) {
                int lc = wn*32 + jj*8 + cl;
                float b0 = biasv[np][jj].x, b1 = biasv[np][jj].y;
                uint32_t base = R2 + (uint32_t)np * 24576u;
                uint32_t w0 = 0u, w1 = 0u;
                if (r < 81)
                    w0 = pack2(mishf(acc[i][jj][0] + b0), mishf(acc[i][jj][1] + b1));
                if (r + 8 < 81)
                    w1 = pack2(mishf(acc[i][jj][2] + b0), mishf(acc[i][jj][3] + b1));
                *(uint32_t*)(sm + base + swz256((uint32_t)(r * 256 + lc * 2))) = w0;
                *(uint32_t*)(sm + base + swz256((uint32_t)((r + 8) * 256 + lc * 2))) = w1;
            }
        }
    }

    // ---- GEMM2 (S n-halves) fused with GEMM3 ----
    pf16(sbase + BUFG2, g_W2, 0, 1, tid);     // X dead; GEMM2 c1
    float acc3[3][3][4] = {};
    for (int np = 0; np < 2; ++np) {
        float acc[3][4][4] = {};
        #pragma unroll
        for (int kc = 0; kc < 4; ++kc) {
            int u = np * 4 + kc;
            cp_wait<0>();
            __syncthreads();
            if (u < 7) { int v = u + 1; pf16(sbase + ((v & 1) ? BUFG2 : R3), g_W2, v >> 2, v & 3, tid); }
            mma_g12<1>(acc, sbase, kc, (u & 1) ? BUFG2 : R3, lane, wm, wn);
        }
        __syncthreads();
        // S-stage epilogue: fp16 [96][256B] swz256 @R1 (rows<81 from acc; 81-95 SEXT/zero)
        #pragma unroll
        for (int i = 0; i < 3; ++i) {
            int r = wm*48 + i*16 + rl;
            #pragma unroll
            for (int jj = 0; jj < 4; ++jj) {
                int lc = wn*32 + jj*8 + cl;
                if (r < 81)
                    *(uint32_t*)(sm + R1 + swz256((uint32_t)(r * 256 + lc * 2))) =
                        pack2(acc[i][jj][0], acc[i][jj][1]);
                if (r + 8 < 81)
                    *(uint32_t*)(sm + R1 + swz256((uint32_t)((r + 8) * 256 + lc * 2))) =
                        pack2(acc[i][jj][2], acc[i][jj][3]);
            }
        }
        if (tid < 240) {                       // rows 81-90 = SEXT cols np*128.., 91-95 zero
            int t = tid >> 4, cc = tid & 15;
            uint4 v = make_uint4(0u, 0u, 0u, 0u);
            if (t < 10) v = *(const uint4*)&g_SEXT[t * 256 + np * 128 + cc * 8];
            *(uint4*)(sm + R1 + swz256((uint32_t)((81 + t) * 256 + cc * 16))) = v;
        }
        __syncthreads();
        gemm3_part(acc3, sbase, np * 2,     lane, wm, wn);
        gemm3_part(acc3, sbase, np * 2 + 1, lane, wm, wn);
    }
    __syncthreads();

    // ---- board staging: f32 [96][BST] @ R1+12288 (conflict-free stride) ----
    {
        float* stag = (float*)(sm + OFF_BOARD);
        #pragma unroll
        for (int i = 0; i < 3; ++i) {
            int r = wm*48 + i*16 + rl;
            #pragma unroll
            for (int jb = 0; jb < 3; ++jb) {
                int col = wn*24 + jb*8 + cl;
                stag[r * BST + col]           = acc3[i][jb][0];
                stag[r * BST + col + 1]       = acc3[i][jb][1];
                stag[(r + 8) * BST + col]     = acc3[i][jb][2];
                stag[(r + 8) * BST + col + 1] = acc3[i][jb][3];
            }
        }
    }
    __syncthreads();

    // ---- fixups: fold constants into aux rows ----
    {
        float* bs = (float*)(sm + OFF_BOARD);
        float cQK  = g_CONST[0];
        float ckwp = g_CONST[8];
        for (int t = tid; t < 729; t += 256) {
            if (t < 81)       bs[90 * BST + t] += cQK;
            else if (t < 162) { int k = t - 81; bs[91 * BST + k] = bs[89 * BST + k] + bs[88 * BST + k] + ckwp; }
            else              { int u2 = t - 162; int n = u2 / 81, k = u2 - n * 81;
                                bs[(81 + n) * BST + k] += g_CONST[1 + n]; }
        }
    }
    __syncthreads();

    // ---- permuted gather: 2 policies per thread via int4 map loads ----
    {
        const float* bs = (const float*)(sm + OFF_BOARD);
        float* ob = out + (size_t)b * NPOL;
        for (int p = tid * 2; p < NPOL; p += 512) {     // NPOL odd: last pair uses pad slot
            int4 m = *(const int4*)&g_MAP2[p];
            float v0 = bs[m.x & 0xffff] + bs[m.x >> 16] + bs[m.y];
            float v1 = bs[m.z & 0xffff] + bs[m.z >> 16] + bs[m.w];
            ob[p] = v0;
            if (p + 1 < NPOL) ob[p + 1] = v1;
        }
    }
}

// ---------------- launch ----------------
extern "C" void kernel_launch(void* const* d_in, const int* in_sizes, int n_in,
                              void* d_out, int out_size) {
    const float* x   = (const float*)d_in[0];
    const float* We  = (const float*)d_in[1];
    const float* be  = (const float*)d_in[2];
    const float* Wq  = (const float*)d_in[3];
    const float* bq  = (const float*)d_in[4];
    const float* Wk  = (const float*)d_in[5];
    const float* bk  = (const float*)d_in[6];
    const float* Wp  = (const float*)d_in[7];
    const float* bp  = (const float*)d_in[8];
    const float* dq  = (const float*)d_in[9];
    const void*  raw = d_in[10];
    const void*  pol = d_in[11];
    float* out = (float*)d_out;

    cudaFuncSetAttribute(k_fused, cudaFuncAttributeMaxDynamicSharedMemorySize, SMEM_TOT);

    prep_all<<<529, 256>>>(We, Wq, Wk, Wp, bq, bk, bp, dq, raw, pol);
    k_fused<<<NB, 256, SMEM_TOT>>>(x, be, out);
}